// round 12
// baseline (speedup 1.0000x reference)
#include <cuda_runtime.h>

#define NB 2
#define SB 1024
#define HB 12
#define DB 64
#define HID (HB*DB)            // 768
#define NCHUNK 32              // split-K chunks for pv + psum
#define SCHUNK (SB/NCHUNK)     // 32
#define ROWS_IT 16             // s-rows per barrier period
#define LCHUNK 16

#define PPV_ELEMS (NB*SB*HB*DB*DB)   // 100663296
#define Z_OFF PPV_ELEMS

__device__ float g_p[NB*SB*HID];                  // p feature map [n][s][h*64+d]
__device__ float g_psumpart[NCHUNK*NB*HB*DB];     // psum partials [c][n][h][d]
__device__ float g_psum[NB*HID];                  // psum [n][h*64+d]
__device__ float g_pvpart[NCHUNK*NB*HB*DB*DB];    // split-K partials
__device__ float g_pv[NB*HB*DB*DB];               // pv[n][h][m][d] (head_mask applied)

__device__ __forceinline__ float elu1(float x) {
    return x > 0.f ? x + 1.f : __expf(x);
}
__device__ __forceinline__ float4 elu1_4(float4 x, float m) {
    float4 r;
    r.x = elu1(x.x) * m; r.y = elu1(x.y) * m;
    r.z = elu1(x.z) * m; r.w = elu1(x.w) * m;
    return r;
}

// ---------------------------------------------------------------------------
// K1: fused feature-map + pv partials + psum partials (R9 structure).
// Per-batch: grid (NCHUNK=32, HB) = 384 CTAs, 256 threads, 4x4 register tile
// ---------------------------------------------------------------------------
__global__ void k_pv(const float* __restrict__ v,
                     const float* __restrict__ pw,
                     const float* __restrict__ mask, int n) {
    int c = blockIdx.x, h = blockIdx.y;
    int t = threadIdx.x;
    int tm = t >> 4;
    int td = t & 15;

    __shared__ float vs[ROWS_IT][DB];
    __shared__ float ps[ROWS_IT][DB];

    float acc[4][4];
    #pragma unroll
    for (int i = 0; i < 4; i++)
        #pragma unroll
        for (int j = 0; j < 4; j++) acc[i][j] = 0.f;
    float psacc = 0.f;

    int s0 = c * SCHUNK;
    #pragma unroll
    for (int so = 0; so < SCHUNK; so += ROWS_IT) {
        // 128 threads load v (16 rows x 16 f4, 2 each), 128 compute p
        {
            int which = t >> 7;          // 0: v, 1: p from pw
            int slot  = t & 127;
            #pragma unroll
            for (int rep = 0; rep < 2; rep++) {
                int idx  = slot + rep * 128;       // 0..255
                int row  = idx >> 4;
                int col4 = idx & 15;
                int s = s0 + so + row;
                if (which == 0) {
                    size_t g4 = ((size_t)((n * SB + s) * HB + h) * DB) / 4 + col4;
                    *reinterpret_cast<float4*>(&vs[row][col4 * 4]) =
                        reinterpret_cast<const float4*>(v)[g4];
                } else {
                    float4 x = reinterpret_cast<const float4*>(pw)[((size_t)s * HID + h * DB) / 4 + col4];
                    float4 pval = elu1_4(x, mask[n * SB + s]);
                    *reinterpret_cast<float4*>(&ps[row][col4 * 4]) = pval;
                    reinterpret_cast<float4*>(g_p)[((size_t)(n * SB + s) * HID + h * DB) / 4 + col4] = pval;
                }
            }
        }
        __syncthreads();
        #pragma unroll
        for (int ss = 0; ss < ROWS_IT; ss++) {
            float4 vr = *reinterpret_cast<const float4*>(&vs[ss][tm * 4]);
            float4 pr = *reinterpret_cast<const float4*>(&ps[ss][td * 4]);
            float vv[4] = {vr.x, vr.y, vr.z, vr.w};
            float pp[4] = {pr.x, pr.y, pr.z, pr.w};
            #pragma unroll
            for (int i = 0; i < 4; i++)
                #pragma unroll
                for (int j = 0; j < 4; j++) acc[i][j] += vv[i] * pp[j];
        }
        if (t < DB) {
            #pragma unroll
            for (int ss = 0; ss < ROWS_IT; ss++) psacc += ps[ss][t];
        }
        __syncthreads();
    }

    // vectorized partials writeback: acc[i][0..3] is one float4
    float4* out4 = reinterpret_cast<float4*>(
        g_pvpart + (size_t)c * (NB * HB * DB * DB) + ((size_t)(n * HB + h) << 12));
    #pragma unroll
    for (int i = 0; i < 4; i++)
        out4[(tm * 4 + i) * 16 + td] = make_float4(acc[i][0], acc[i][1], acc[i][2], acc[i][3]);

    if (t < DB)
        g_psumpart[(size_t)c * (NB * HB * DB) + ((n * HB + h) << 6) + t] = psacc;
}

// ---------------------------------------------------------------------------
// K2: combined reduce for one batch n (float4-vectorized, 128-thread blocks)
// covers HB*DB*DB/4 = 12288 pv-float4 + HB*DB/4 = 192 psum-float4
// ---------------------------------------------------------------------------
__global__ void k_reduce(const float* __restrict__ head_mask, int n) {
    int idx = blockIdx.x * blockDim.x + threadIdx.x;
    const int PV4 = NB * HB * DB * DB / 4;    // full stride per chunk
    const int PV4N = HB * DB * DB / 4;        // 12288 per batch
    const int PS4N = HB * DB / 4;             // 192 per batch
    int base = n * PV4N;
    if (idx < PV4N) {
        float4 acc = make_float4(0.f, 0.f, 0.f, 0.f);
        #pragma unroll
        for (int c = 0; c < NCHUNK; c++) {
            float4 x = reinterpret_cast<const float4*>(g_pvpart)[(size_t)c * PV4 + base + idx];
            acc.x += x.x; acc.y += x.y; acc.z += x.z; acc.w += x.w;
        }
        int h = (idx >> 10);                  // idx*4/4096, 0..11
        float hm = head_mask[h];
        acc.x *= hm; acc.y *= hm; acc.z *= hm; acc.w *= hm;
        reinterpret_cast<float4*>(g_pv)[base + idx] = acc;
    } else if (idx < PV4N + PS4N) {
        int j = idx - PV4N;
        float4 acc = make_float4(0.f, 0.f, 0.f, 0.f);
        #pragma unroll
        for (int c = 0; c < NCHUNK; c++) {
            float4 x = reinterpret_cast<const float4*>(g_psumpart)[(size_t)c * (NB * HB * DB / 4) + n * PS4N + j];
            acc.x += x.x; acc.y += x.y; acc.z += x.z; acc.w += x.w;
        }
        reinterpret_cast<float4*>(g_psum)[n * PS4N + j] = acc;
    }
}

// ---------------------------------------------------------------------------
// K3 (dominant, store-bound) — logic unchanged, n passed as parameter.
// ppv[n,l,h,m,d] = p[n,l,h,d] * pv[n,h,m,d]; fused z_pp.
// ---------------------------------------------------------------------------
__device__ __forceinline__ void stg_cs_v8(float* p, float4 a, float4 b) {
    asm volatile("st.global.cs.v8.f32 [%0], {%1,%2,%3,%4,%5,%6,%7,%8};"
                 :: "l"(p), "f"(a.x), "f"(a.y), "f"(a.z), "f"(a.w),
                    "f"(b.x), "f"(b.y), "f"(b.z), "f"(b.w) : "memory");
}

__global__ void __launch_bounds__(256, 6) k_ppv(float* __restrict__ out, int n) {
    int l0 = blockIdx.x * LCHUNK;
    int h  = blockIdx.y;
    int t  = threadIdx.x;

    __shared__ float4 pv_sh[DB * DB / 4];     // 16KB
    __shared__ float4 p_sh[LCHUNK * DB / 4];  // 4KB
    __shared__ float4 ps_sh[DB / 4];          // 256B

    {
        const float4* pv4 = reinterpret_cast<const float4*>(g_pv)
                          + (size_t)(n * HB + h) * (DB * DB / 4);
        #pragma unroll
        for (int i = 0; i < 4; i++) pv_sh[t + 256 * i] = pv4[t + 256 * i];
    }
    {
        int li  = t >> 4;
        int d4  = t & 15;
        const float4* p4 = reinterpret_cast<const float4*>(g_p);
        p_sh[t] = p4[((size_t)((n * SB + l0 + li) * HB + h) * DB) / 4 + d4];
    }
    if (t < DB / 4) {
        ps_sh[t] = reinterpret_cast<const float4*>(g_psum)[(n * HID + h * DB) / 4 + t];
    }
    __syncthreads();

    // fused z: 16-lane segmented dot products
    {
        int li = t >> 4;
        int j  = t & 15;
        float4 pp = p_sh[(li << 4) + j];
        float4 ss = ps_sh[j];
        float a = pp.x * ss.x + pp.y * ss.y + pp.z * ss.z + pp.w * ss.w;
        a += __shfl_down_sync(0xffffffffu, a, 8, 16);
        a += __shfl_down_sync(0xffffffffu, a, 4, 16);
        a += __shfl_down_sync(0xffffffffu, a, 2, 16);
        a += __shfl_down_sync(0xffffffffu, a, 1, 16);
        if (j == 0)
            out[Z_OFF + (size_t)(n * SB + l0 + li) * HB + h] = a + 1e-6f;
    }

    float4 va0 = pv_sh[2 * t];
    float4 va1 = pv_sh[2 * t + 1];
    float4 vb0 = pv_sh[2 * t + 512];
    float4 vb1 = pv_sh[2 * t + 513];
    int da0 = (2 * t) & 15, da1 = (2 * t + 1) & 15;

    #pragma unroll 2
    for (int li = 0; li < LCHUNK; li++) {
        float* ob = out + (size_t)((n * SB + l0 + li) * HB + h) * (DB * DB);
        float4 pa0 = p_sh[(li << 4) + da0];
        float4 pa1 = p_sh[(li << 4) + da1];
        float4 r0, r1;
        r0.x = pa0.x * va0.x; r0.y = pa0.y * va0.y; r0.z = pa0.z * va0.z; r0.w = pa0.w * va0.w;
        r1.x = pa1.x * va1.x; r1.y = pa1.y * va1.y; r1.z = pa1.z * va1.z; r1.w = pa1.w * va1.w;
        stg_cs_v8(ob + 8 * t, r0, r1);
        float4 s0, s1;
        s0.x = pa0.x * vb0.x; s0.y = pa0.y * vb0.y; s0.z = pa0.z * vb0.z; s0.w = pa0.w * vb0.w;
        s1.x = pa1.x * vb1.x; s1.y = pa1.y * vb1.y; s1.z = pa1.z * vb1.z; s1.w = pa1.w * vb1.w;
        stg_cs_v8(ob + 8 * t + 2048, s0, s1);
    }
}

// ---------------------------------------------------------------------------
// Two independent per-batch chains (n=0 on capture/legacy stream, n=1 on a
// forked stream). Streams/events are host objects (no device memory); they
// are created fresh each call and intentionally not destroyed (capture may
// still reference them until EndCapture).
// ---------------------------------------------------------------------------
extern "C" void kernel_launch(void* const* d_in, const int* in_sizes, int n_in,
                              void* d_out, int out_size) {
    // inputs (metadata order): q, v, attention_mask, head_mask, pos_weight
    const float* v         = (const float*)d_in[1];
    const float* mask      = (const float*)d_in[2];
    const float* head_mask = (const float*)d_in[3];
    const float* pw        = (const float*)d_in[4];
    float* out = (float*)d_out;

    const int RED_BLOCKS = (HB * DB * DB / 4 + HB * DB / 4 + 127) / 128;   // 98

    cudaStream_t s2;
    cudaStreamCreate(&s2);
    cudaEvent_t eFork, eJoin;
    cudaEventCreateWithFlags(&eFork, cudaEventDisableTiming);
    cudaEventCreateWithFlags(&eJoin, cudaEventDisableTiming);

    // fork: s2 branches off the (possibly capturing) legacy stream
    cudaEventRecord(eFork, 0);
    cudaStreamWaitEvent(s2, eFork, 0);

    // n = 1 chain on s2
    k_pv<<<dim3(NCHUNK, HB), 256, 0, s2>>>(v, pw, mask, 1);
    k_reduce<<<RED_BLOCKS, 128, 0, s2>>>(head_mask, 1);
    k_ppv<<<dim3(SB / LCHUNK, HB), 256, 0, s2>>>(out, 1);

    // n = 0 chain on the legacy stream
    k_pv<<<dim3(NCHUNK, HB), 256>>>(v, pw, mask, 0);
    k_reduce<<<RED_BLOCKS, 128>>>(head_mask, 0);
    k_ppv<<<dim3(SB / LCHUNK, HB), 256>>>(out, 0);

    // join
    cudaEventRecord(eJoin, s2);
    cudaStreamWaitEvent(0, eJoin, 0);
}

// round 13
// speedup vs baseline: 1.0735x; 1.0735x over previous
#include <cuda_runtime.h>

#define NB 2
#define SB 1024
#define HB 12
#define DB 64
#define HID (HB*DB)            // 768
#define NCHUNK 32              // split-K chunks for pv + psum
#define SCHUNK (SB/NCHUNK)     // 32
#define ROWS_IT 16             // s-rows per barrier period
#define LCHUNK 16

#define PPV_ELEMS (NB*SB*HB*DB*DB)   // 100663296
#define Z_OFF PPV_ELEMS

__device__ float g_p[NB*SB*HID];                  // p feature map [n][s][h*64+d]
__device__ float g_psumpart[NCHUNK*NB*HB*DB];     // psum partials [c][n][h][d]
__device__ float g_psum[NB*HID];                  // psum [n][h*64+d]
__device__ float g_pvpart[NCHUNK*NB*HB*DB*DB];    // split-K partials
__device__ float g_pv[NB*HB*DB*DB];               // pv[n][h][m][d] (head_mask applied)

__device__ __forceinline__ float elu1(float x) {
    return x > 0.f ? x + 1.f : expf(x);
}
__device__ __forceinline__ float4 elu1_4(float4 x, float m) {
    float4 r;
    r.x = elu1(x.x) * m; r.y = elu1(x.y) * m;
    r.z = elu1(x.z) * m; r.w = elu1(x.w) * m;
    return r;
}

// ---------------------------------------------------------------------------
// K1: fused feature-map + pv partials + psum partials.
//   Balanced load phase: every thread loads 1 v-float4 AND computes 1 p-float4
//   per period (expf spread across all warps; no idle half-block).
//   Outer loop kept at unroll 1 to pin register pressure (R10 lesson).
// grid (NCHUNK=32, H, N) = 768 CTAs, 256 threads, 4x4 register tile
// ---------------------------------------------------------------------------
__global__ void k_pv(const float* __restrict__ v,
                     const float* __restrict__ pw,
                     const float* __restrict__ mask) {
    int c = blockIdx.x, h = blockIdx.y, n = blockIdx.z;
    int t = threadIdx.x;
    int tm = t >> 4;
    int td = t & 15;

    __shared__ float vs[ROWS_IT][DB];
    __shared__ float ps[ROWS_IT][DB];

    float acc[4][4];
    #pragma unroll
    for (int i = 0; i < 4; i++)
        #pragma unroll
        for (int j = 0; j < 4; j++) acc[i][j] = 0.f;
    float psacc = 0.f;

    int s0 = c * SCHUNK;
    int row  = t >> 4;     // 0..15
    int col4 = t & 15;     // 0..15

    #pragma unroll 1
    for (int so = 0; so < SCHUNK; so += ROWS_IT) {
        // balanced load phase: each thread handles slot (row, col4) for BOTH arrays
        {
            int s = s0 + so + row;
            size_t vg4 = ((size_t)((n * SB + s) * HB + h) * DB) / 4 + col4;
            *reinterpret_cast<float4*>(&vs[row][col4 * 4]) =
                reinterpret_cast<const float4*>(v)[vg4];
            float4 x = reinterpret_cast<const float4*>(pw)[((size_t)s * HID + h * DB) / 4 + col4];
            float4 pval = elu1_4(x, mask[n * SB + s]);
            *reinterpret_cast<float4*>(&ps[row][col4 * 4]) = pval;
            reinterpret_cast<float4*>(g_p)[((size_t)(n * SB + s) * HID + h * DB) / 4 + col4] = pval;
        }
        __syncthreads();
        #pragma unroll
        for (int ss = 0; ss < ROWS_IT; ss++) {
            float4 vr = *reinterpret_cast<const float4*>(&vs[ss][tm * 4]);
            float4 pr = *reinterpret_cast<const float4*>(&ps[ss][td * 4]);
            float vv[4] = {vr.x, vr.y, vr.z, vr.w};
            float pp[4] = {pr.x, pr.y, pr.z, pr.w};
            #pragma unroll
            for (int i = 0; i < 4; i++)
                #pragma unroll
                for (int j = 0; j < 4; j++) acc[i][j] += vv[i] * pp[j];
        }
        if (t < DB) {
            #pragma unroll
            for (int ss = 0; ss < ROWS_IT; ss++) psacc += ps[ss][t];
        }
        __syncthreads();
    }

    // vectorized partials writeback: acc[i][0..3] is one float4
    float4* out4 = reinterpret_cast<float4*>(
        g_pvpart + (size_t)c * (NB * HB * DB * DB) + ((size_t)(n * HB + h) << 12));
    #pragma unroll
    for (int i = 0; i < 4; i++)
        out4[(tm * 4 + i) * 16 + td] = make_float4(acc[i][0], acc[i][1], acc[i][2], acc[i][3]);

    if (t < DB)
        g_psumpart[(size_t)c * (NB * HB * DB) + ((n * HB + h) << 6) + t] = psacc;
}

// ---------------------------------------------------------------------------
// K2: combined reduce (float4-vectorized, 128-thread blocks -> 390 CTAs)
// ---------------------------------------------------------------------------
__global__ void k_reduce(const float* __restrict__ head_mask) {
    int idx = blockIdx.x * blockDim.x + threadIdx.x;
    const int PV4 = NB * HB * DB * DB / 4;   // 24576
    const int PS4 = NB * HID / 4;            // 384
    if (idx < PV4) {
        float4 acc = make_float4(0.f, 0.f, 0.f, 0.f);
        #pragma unroll
        for (int c = 0; c < NCHUNK; c++) {
            float4 x = reinterpret_cast<const float4*>(g_pvpart)[(size_t)c * PV4 + idx];
            acc.x += x.x; acc.y += x.y; acc.z += x.z; acc.w += x.w;
        }
        int h = (idx >> 10) % HB;
        float hm = head_mask[h];
        acc.x *= hm; acc.y *= hm; acc.z *= hm; acc.w *= hm;
        reinterpret_cast<float4*>(g_pv)[idx] = acc;
    } else if (idx < PV4 + PS4) {
        int j = idx - PV4;
        float4 acc = make_float4(0.f, 0.f, 0.f, 0.f);
        #pragma unroll
        for (int c = 0; c < NCHUNK; c++) {
            float4 x = reinterpret_cast<const float4*>(g_psumpart)[(size_t)c * (NB * HB * DB / 4) + j];
            acc.x += x.x; acc.y += x.y; acc.z += x.z; acc.w += x.w;
        }
        reinterpret_cast<float4*>(g_psum)[j] = acc;
    }
}

// ---------------------------------------------------------------------------
// K3 (dominant, store-bound) — UNCHANGED (at HBM write roofline, 39 regs).
// ppv[n,l,h,m,d] = p[n,l,h,d] * pv[n,h,m,d]; fused z_pp.
// ---------------------------------------------------------------------------
__device__ __forceinline__ void stg_cs_v8(float* p, float4 a, float4 b) {
    asm volatile("st.global.cs.v8.f32 [%0], {%1,%2,%3,%4,%5,%6,%7,%8};"
                 :: "l"(p), "f"(a.x), "f"(a.y), "f"(a.z), "f"(a.w),
                    "f"(b.x), "f"(b.y), "f"(b.z), "f"(b.w) : "memory");
}

__global__ void __launch_bounds__(256, 6) k_ppv(float* __restrict__ out) {
    int l0 = blockIdx.x * LCHUNK;
    int h  = blockIdx.y;
    int n  = blockIdx.z;
    int t  = threadIdx.x;

    __shared__ float4 pv_sh[DB * DB / 4];     // 16KB
    __shared__ float4 p_sh[LCHUNK * DB / 4];  // 4KB
    __shared__ float4 ps_sh[DB / 4];          // 256B

    {
        const float4* pv4 = reinterpret_cast<const float4*>(g_pv)
                          + (size_t)(n * HB + h) * (DB * DB / 4);
        #pragma unroll
        for (int i = 0; i < 4; i++) pv_sh[t + 256 * i] = pv4[t + 256 * i];
    }
    {
        int li  = t >> 4;
        int d4  = t & 15;
        const float4* p4 = reinterpret_cast<const float4*>(g_p);
        p_sh[t] = p4[((size_t)((n * SB + l0 + li) * HB + h) * DB) / 4 + d4];
    }
    if (t < DB / 4) {
        ps_sh[t] = reinterpret_cast<const float4*>(g_psum)[(n * HID + h * DB) / 4 + t];
    }
    __syncthreads();

    // fused z: 16-lane segmented dot products
    {
        int li = t >> 4;
        int j  = t & 15;
        float4 pp = p_sh[(li << 4) + j];
        float4 ss = ps_sh[j];
        float a = pp.x * ss.x + pp.y * ss.y + pp.z * ss.z + pp.w * ss.w;
        a += __shfl_down_sync(0xffffffffu, a, 8, 16);
        a += __shfl_down_sync(0xffffffffu, a, 4, 16);
        a += __shfl_down_sync(0xffffffffu, a, 2, 16);
        a += __shfl_down_sync(0xffffffffu, a, 1, 16);
        if (j == 0)
            out[Z_OFF + (size_t)(n * SB + l0 + li) * HB + h] = a + 1e-6f;
    }

    float4 va0 = pv_sh[2 * t];
    float4 va1 = pv_sh[2 * t + 1];
    float4 vb0 = pv_sh[2 * t + 512];
    float4 vb1 = pv_sh[2 * t + 513];
    int da0 = (2 * t) & 15, da1 = (2 * t + 1) & 15;

    #pragma unroll 2
    for (int li = 0; li < LCHUNK; li++) {
        float* ob = out + (size_t)((n * SB + l0 + li) * HB + h) * (DB * DB);
        float4 pa0 = p_sh[(li << 4) + da0];
        float4 pa1 = p_sh[(li << 4) + da1];
        float4 r0, r1;
        r0.x = pa0.x * va0.x; r0.y = pa0.y * va0.y; r0.z = pa0.z * va0.z; r0.w = pa0.w * va0.w;
        r1.x = pa1.x * va1.x; r1.y = pa1.y * va1.y; r1.z = pa1.z * va1.z; r1.w = pa1.w * va1.w;
        stg_cs_v8(ob + 8 * t, r0, r1);
        float4 s0, s1;
        s0.x = pa0.x * vb0.x; s0.y = pa0.y * vb0.y; s0.z = pa0.z * vb0.z; s0.w = pa0.w * vb0.w;
        s1.x = pa1.x * vb1.x; s1.y = pa1.y * vb1.y; s1.z = pa1.z * vb1.z; s1.w = pa1.w * vb1.w;
        stg_cs_v8(ob + 8 * t + 2048, s0, s1);
    }
}

// ---------------------------------------------------------------------------
extern "C" void kernel_launch(void* const* d_in, const int* in_sizes, int n_in,
                              void* d_out, int out_size) {
    // inputs (metadata order): q, v, attention_mask, head_mask, pos_weight
    const float* v         = (const float*)d_in[1];
    const float* mask      = (const float*)d_in[2];
    const float* head_mask = (const float*)d_in[3];
    const float* pw        = (const float*)d_in[4];
    float* out = (float*)d_out;

    k_pv<<<dim3(NCHUNK, HB, NB), 256>>>(v, pw, mask);
    k_reduce<<<(NB * HB * DB * DB / 4 + NB * HID / 4 + 127) / 128, 128>>>(head_mask);
    k_ppv<<<dim3(SB / LCHUNK, HB, NB), 256>>>(out);
}

// round 14
// speedup vs baseline: 1.0951x; 1.0202x over previous
#include <cuda_runtime.h>

#define NB 2
#define SB 1024
#define HB 12
#define DB 64
#define HID (HB*DB)            // 768
#define NCHUNK 32              // split-K chunks for pv + psum
#define SCHUNK (SB/NCHUNK)     // 32
#define ROWS_IT 16             // s-rows per barrier period
#define LCHUNK 16

#define PPV_ELEMS (NB*SB*HB*DB*DB)   // 100663296
#define Z_OFF PPV_ELEMS

__device__ float g_p[NB*SB*HID];                  // p feature map [n][s][h*64+d]
__device__ float g_psumpart[NCHUNK*NB*HB*DB];     // psum partials [c][n][h][d]
__device__ float g_psum[NB*HID];                  // psum [n][h*64+d]
__device__ float g_pvpart[NCHUNK*NB*HB*DB*DB];    // split-K partials
__device__ float g_pv[NB*HB*DB*DB];               // pv[n][h][m][d] (head_mask applied)

__device__ __forceinline__ float elu1(float x) {
    return x > 0.f ? x + 1.f : expf(x);
}
__device__ __forceinline__ float4 elu1_4(float4 x, float m) {
    float4 r;
    r.x = elu1(x.x) * m; r.y = elu1(x.y) * m;
    r.z = elu1(x.z) * m; r.w = elu1(x.w) * m;
    return r;
}

// ---------------------------------------------------------------------------
// K1: fused feature-map + pv partials + psum partials.
//   Balanced load phase (R13) + __launch_bounds__(256,5): 51-reg budget so
//   5 CTAs/SM fit -> 740 of 768 CTAs in wave 1 (was 4/SM, 176-CTA tail wave).
// grid (NCHUNK=32, H, N) = 768 CTAs, 256 threads, 4x4 register tile
// ---------------------------------------------------------------------------
__global__ void __launch_bounds__(256, 5) k_pv(const float* __restrict__ v,
                                               const float* __restrict__ pw,
                                               const float* __restrict__ mask) {
    int c = blockIdx.x, h = blockIdx.y, n = blockIdx.z;
    int t = threadIdx.x;
    int tm = t >> 4;
    int td = t & 15;

    __shared__ float vs[ROWS_IT][DB];
    __shared__ float ps[ROWS_IT][DB];

    float acc[4][4];
    #pragma unroll
    for (int i = 0; i < 4; i++)
        #pragma unroll
        for (int j = 0; j < 4; j++) acc[i][j] = 0.f;
    float psacc = 0.f;

    int s0 = c * SCHUNK;
    int row  = t >> 4;     // 0..15
    int col4 = t & 15;     // 0..15

    #pragma unroll 1
    for (int so = 0; so < SCHUNK; so += ROWS_IT) {
        // balanced load phase: each thread handles slot (row, col4) for BOTH arrays
        {
            int s = s0 + so + row;
            size_t vg4 = ((size_t)((n * SB + s) * HB + h) * DB) / 4 + col4;
            *reinterpret_cast<float4*>(&vs[row][col4 * 4]) =
                reinterpret_cast<const float4*>(v)[vg4];
            float4 x = reinterpret_cast<const float4*>(pw)[((size_t)s * HID + h * DB) / 4 + col4];
            float4 pval = elu1_4(x, mask[n * SB + s]);
            *reinterpret_cast<float4*>(&ps[row][col4 * 4]) = pval;
            reinterpret_cast<float4*>(g_p)[((size_t)(n * SB + s) * HID + h * DB) / 4 + col4] = pval;
        }
        __syncthreads();
        #pragma unroll
        for (int ss = 0; ss < ROWS_IT; ss++) {
            float4 vr = *reinterpret_cast<const float4*>(&vs[ss][tm * 4]);
            float4 pr = *reinterpret_cast<const float4*>(&ps[ss][td * 4]);
            float vv[4] = {vr.x, vr.y, vr.z, vr.w};
            float pp[4] = {pr.x, pr.y, pr.z, pr.w};
            #pragma unroll
            for (int i = 0; i < 4; i++)
                #pragma unroll
                for (int j = 0; j < 4; j++) acc[i][j] += vv[i] * pp[j];
        }
        if (t < DB) {
            #pragma unroll
            for (int ss = 0; ss < ROWS_IT; ss++) psacc += ps[ss][t];
        }
        __syncthreads();
    }

    // vectorized partials writeback: acc[i][0..3] is one float4
    float4* out4 = reinterpret_cast<float4*>(
        g_pvpart + (size_t)c * (NB * HB * DB * DB) + ((size_t)(n * HB + h) << 12));
    #pragma unroll
    for (int i = 0; i < 4; i++)
        out4[(tm * 4 + i) * 16 + td] = make_float4(acc[i][0], acc[i][1], acc[i][2], acc[i][3]);

    if (t < DB)
        g_psumpart[(size_t)c * (NB * HB * DB) + ((n * HB + h) << 6) + t] = psacc;
}

// ---------------------------------------------------------------------------
// K2: combined reduce (float4-vectorized, 128-thread blocks -> 390 CTAs)
// ---------------------------------------------------------------------------
__global__ void k_reduce(const float* __restrict__ head_mask) {
    int idx = blockIdx.x * blockDim.x + threadIdx.x;
    const int PV4 = NB * HB * DB * DB / 4;   // 24576
    const int PS4 = NB * HID / 4;            // 384
    if (idx < PV4) {
        float4 acc = make_float4(0.f, 0.f, 0.f, 0.f);
        #pragma unroll
        for (int c = 0; c < NCHUNK; c++) {
            float4 x = reinterpret_cast<const float4*>(g_pvpart)[(size_t)c * PV4 + idx];
            acc.x += x.x; acc.y += x.y; acc.z += x.z; acc.w += x.w;
        }
        int h = (idx >> 10) % HB;
        float hm = head_mask[h];
        acc.x *= hm; acc.y *= hm; acc.z *= hm; acc.w *= hm;
        reinterpret_cast<float4*>(g_pv)[idx] = acc;
    } else if (idx < PV4 + PS4) {
        int j = idx - PV4;
        float4 acc = make_float4(0.f, 0.f, 0.f, 0.f);
        #pragma unroll
        for (int c = 0; c < NCHUNK; c++) {
            float4 x = reinterpret_cast<const float4*>(g_psumpart)[(size_t)c * (NB * HB * DB / 4) + j];
            acc.x += x.x; acc.y += x.y; acc.z += x.z; acc.w += x.w;
        }
        reinterpret_cast<float4*>(g_psum)[j] = acc;
    }
}

// ---------------------------------------------------------------------------
// K3 (dominant, store-bound) — UNCHANGED (at HBM write roofline, 39 regs).
// ppv[n,l,h,m,d] = p[n,l,h,d] * pv[n,h,m,d]; fused z_pp.
// ---------------------------------------------------------------------------
__device__ __forceinline__ void stg_cs_v8(float* p, float4 a, float4 b) {
    asm volatile("st.global.cs.v8.f32 [%0], {%1,%2,%3,%4,%5,%6,%7,%8};"
                 :: "l"(p), "f"(a.x), "f"(a.y), "f"(a.z), "f"(a.w),
                    "f"(b.x), "f"(b.y), "f"(b.z), "f"(b.w) : "memory");
}

__global__ void __launch_bounds__(256, 6) k_ppv(float* __restrict__ out) {
    int l0 = blockIdx.x * LCHUNK;
    int h  = blockIdx.y;
    int n  = blockIdx.z;
    int t  = threadIdx.x;

    __shared__ float4 pv_sh[DB * DB / 4];     // 16KB
    __shared__ float4 p_sh[LCHUNK * DB / 4];  // 4KB
    __shared__ float4 ps_sh[DB / 4];          // 256B

    {
        const float4* pv4 = reinterpret_cast<const float4*>(g_pv)
                          + (size_t)(n * HB + h) * (DB * DB / 4);
        #pragma unroll
        for (int i = 0; i < 4; i++) pv_sh[t + 256 * i] = pv4[t + 256 * i];
    }
    {
        int li  = t >> 4;
        int d4  = t & 15;
        const float4* p4 = reinterpret_cast<const float4*>(g_p);
        p_sh[t] = p4[((size_t)((n * SB + l0 + li) * HB + h) * DB) / 4 + d4];
    }
    if (t < DB / 4) {
        ps_sh[t] = reinterpret_cast<const float4*>(g_psum)[(n * HID + h * DB) / 4 + t];
    }
    __syncthreads();

    // fused z: 16-lane segmented dot products
    {
        int li = t >> 4;
        int j  = t & 15;
        float4 pp = p_sh[(li << 4) + j];
        float4 ss = ps_sh[j];
        float a = pp.x * ss.x + pp.y * ss.y + pp.z * ss.z + pp.w * ss.w;
        a += __shfl_down_sync(0xffffffffu, a, 8, 16);
        a += __shfl_down_sync(0xffffffffu, a, 4, 16);
        a += __shfl_down_sync(0xffffffffu, a, 2, 16);
        a += __shfl_down_sync(0xffffffffu, a, 1, 16);
        if (j == 0)
            out[Z_OFF + (size_t)(n * SB + l0 + li) * HB + h] = a + 1e-6f;
    }

    float4 va0 = pv_sh[2 * t];
    float4 va1 = pv_sh[2 * t + 1];
    float4 vb0 = pv_sh[2 * t + 512];
    float4 vb1 = pv_sh[2 * t + 513];
    int da0 = (2 * t) & 15, da1 = (2 * t + 1) & 15;

    #pragma unroll 2
    for (int li = 0; li < LCHUNK; li++) {
        float* ob = out + (size_t)((n * SB + l0 + li) * HB + h) * (DB * DB);
        float4 pa0 = p_sh[(li << 4) + da0];
        float4 pa1 = p_sh[(li << 4) + da1];
        float4 r0, r1;
        r0.x = pa0.x * va0.x; r0.y = pa0.y * va0.y; r0.z = pa0.z * va0.z; r0.w = pa0.w * va0.w;
        r1.x = pa1.x * va1.x; r1.y = pa1.y * va1.y; r1.z = pa1.z * va1.z; r1.w = pa1.w * va1.w;
        stg_cs_v8(ob + 8 * t, r0, r1);
        float4 s0, s1;
        s0.x = pa0.x * vb0.x; s0.y = pa0.y * vb0.y; s0.z = pa0.z * vb0.z; s0.w = pa0.w * vb0.w;
        s1.x = pa1.x * vb1.x; s1.y = pa1.y * vb1.y; s1.z = pa1.z * vb1.z; s1.w = pa1.w * vb1.w;
        stg_cs_v8(ob + 8 * t + 2048, s0, s1);
    }
}

// ---------------------------------------------------------------------------
extern "C" void kernel_launch(void* const* d_in, const int* in_sizes, int n_in,
                              void* d_out, int out_size) {
    // inputs (metadata order): q, v, attention_mask, head_mask, pos_weight
    const float* v         = (const float*)d_in[1];
    const float* mask      = (const float*)d_in[2];
    const float* head_mask = (const float*)d_in[3];
    const float* pw        = (const float*)d_in[4];
    float* out = (float*)d_out;

    k_pv<<<dim3(NCHUNK, HB, NB), 256>>>(v, pw, mask);
    k_reduce<<<(NB * HB * DB * DB / 4 + NB * HID / 4 + 127) / 128, 128>>>(head_mask);
    k_ppv<<<dim3(SB / LCHUNK, HB, NB), 256>>>(out);
}